// round 8
// baseline (speedup 1.0000x reference)
#include <cuda_runtime.h>
#include <math.h>
#include <stdint.h>

typedef unsigned long long ull;

// Problem constants
constexpr int S_   = 128;   // sequence length
constexpr int B_   = 64;    // batch
constexpr int E_   = 256;   // embedding dim
constexpr int H_   = 256;   // hidden
constexpr int G4_  = 1024;  // 4*H (gates)
constexpr int HID_ = 30;    // attention hidden
constexpr int NCTA_DIR = 64;   // CTAs per direction in persistent step kernel

// Scratch (static device globals — no runtime allocation)
__device__ float g_emb[S_ * B_ * E_];        // (t,b,e)
__device__ float g_embT[E_ * S_ * B_];       // transposed: [e][t*B+b]
__device__ float g_WihT[2 * E_ * G4_];       // transposed Wih per dir: [k][n]
__device__ float g_X[2 * S_ * B_ * G4_];     // x-projections per dir, bias folded in
__device__ float g_h[2 * S_ * B_ * H_];      // [dir][t][b][k]  (for K4)
__device__ float g_hT[2][2][H_][B_];         // ping-pong [dir][parity][k][b]
__device__ int   g_flag[2][NCTA_DIR];        // per-CTA progress flags (monotone step count)
__device__ float g_U[B_ * S_ * HID_];        // u = enc @ Ua^T
__device__ float g_Wt[B_ * HID_ * S_];       // w transposed: [b][k][s]

// fast activations: MUFU-based, rel err ~2e-7 (budget is 1e-3)
__device__ __forceinline__ float fsig(float x)  { return 1.0f / (1.0f + __expf(-x)); }
__device__ __forceinline__ float ftanh(float x) { return 2.0f / (1.0f + __expf(-2.0f * x)) - 1.0f; }

// pure (non-volatile) packed fp32 math — scheduler may move these freely
__device__ __forceinline__ void ffma2(ull& d, ull a, ull b) {
    asm("fma.rn.f32x2 %0, %1, %2, %0;" : "+l"(d) : "l"(a), "l"(b));
}
__device__ __forceinline__ ull pack2(float lo, float hi) {
    ull r; asm("mov.b64 %0, {%1, %2};" : "=l"(r) : "f"(lo), "f"(hi)); return r;
}
__device__ __forceinline__ float2 unpack2(ull v) {
    float2 r; asm("mov.b64 {%0, %1}, %2;" : "=f"(r.x), "=f"(r.y) : "l"(v)); return r;
}
__device__ __forceinline__ void stcg32(float* p, float v) {
    asm volatile("st.global.cg.f32 [%0], %1;" :: "l"(p), "f"(v));
}
__device__ __forceinline__ void cp16(uint32_t smem_dst, const void* gsrc) {
    asm volatile("cp.async.cg.shared.global [%0], [%1], 16;" :: "r"(smem_dst), "l"(gsrc) : "memory");
}

// ---------------------------------------------------------------------------
// K0: zero the progress flags (stream-ordered before k_steps)
// ---------------------------------------------------------------------------
__global__ void k_zero_bar() {
    if (threadIdx.x < 2 * NCTA_DIR) (&g_flag[0][0])[threadIdx.x] = 0;
}

// ---------------------------------------------------------------------------
// K1: embedding gather.  grid = S*B blocks, 64 threads (float4 row copy)
// ---------------------------------------------------------------------------
__global__ void k_gather(const int* __restrict__ concepts,
                         const float* __restrict__ table) {
    int tb  = blockIdx.x;                      // t*B + b
    int tok = concepts[tb];
    const float4* src = reinterpret_cast<const float4*>(table + (size_t)tok * E_);
    float4*       dst = reinterpret_cast<float4*>(g_emb + (size_t)tb * E_);
    dst[threadIdx.x] = src[threadIdx.x];
}

// ---------------------------------------------------------------------------
// K1b: tiled transpose  src[M][N] -> dst[N][M]   (M,N multiples of 32)
// ---------------------------------------------------------------------------
__global__ void k_transpose(const float* __restrict__ src, float* __restrict__ dst,
                            int M, int N) {
    __shared__ float t[32][33];
    int nb = blockIdx.x * 32, mb = blockIdx.y * 32;
    int tx = threadIdx.x, ty = threadIdx.y;   // (32, 8)
#pragma unroll
    for (int i = 0; i < 4; i++)
        t[ty + i * 8][tx] = src[(size_t)(mb + ty + i * 8) * N + nb + tx];
    __syncthreads();
#pragma unroll
    for (int i = 0; i < 4; i++)
        dst[(size_t)(nb + ty + i * 8) * M + mb + tx] = t[tx][ty + i * 8];
}

// ---------------------------------------------------------------------------
// K2: x-projection GEMM  X[dir] = emb @ Wih[dir]^T + b[dir]
//     M=8192, N=1024, K=256.  BM=BN=128, BK=16, 256 thr, 8x8 microtile,
//     packed f32x2 FMA.  Sources pre-transposed (g_embT / g_WihT) so tiles
//     load k-major directly via cp.async; 2-stage double buffer.
// ---------------------------------------------------------------------------
__global__ __launch_bounds__(256) void k_xgemm(const float* __restrict__ b_f,
                                               const float* __restrict__ b_b) {
    const int dir = blockIdx.z;
    const float* __restrict__ AT   = g_embT;                      // [k][8192]
    const float* __restrict__ BT   = g_WihT + (size_t)dir * E_ * G4_;  // [k][1024]
    const float* __restrict__ bias = dir ? b_b : b_f;
    float* __restrict__ Xout = g_X + (size_t)dir * S_ * B_ * G4_;

    __shared__ float As[2][16][132];   // [stage][k][m]
    __shared__ float Bs[2][16][132];   // [stage][k][n]

    const int m0  = blockIdx.x * 128;
    const int n0  = blockIdx.y * 128;
    const int tid = threadIdx.x;
    const int tx  = tid & 15;       // -> n
    const int ty  = tid >> 4;       // -> m

    const uint32_t as_sa = (uint32_t)__cvta_generic_to_shared(&As[0][0][0]);
    const uint32_t bs_sa = (uint32_t)__cvta_generic_to_shared(&Bs[0][0][0]);
    const int q0 = tid * 2;
    const int r0q = q0 >> 5, c0q = (q0 & 31) * 4;        // quad 0: row, col4
    const int r1q = (q0 + 1) >> 5, c1q = ((q0 + 1) & 31) * 4;

    auto load_stage = [&](int st, int kc) {
        uint32_t abase = as_sa + st * (16 * 132 * 4);
        uint32_t bbase = bs_sa + st * (16 * 132 * 4);
        cp16(abase + (r0q * 132 + c0q) * 4, AT + (size_t)(kc + r0q) * 8192 + m0 + c0q);
        cp16(abase + (r1q * 132 + c1q) * 4, AT + (size_t)(kc + r1q) * 8192 + m0 + c1q);
        cp16(bbase + (r0q * 132 + c0q) * 4, BT + (size_t)(kc + r0q) * 1024 + n0 + c0q);
        cp16(bbase + (r1q * 132 + c1q) * 4, BT + (size_t)(kc + r1q) * 1024 + n0 + c1q);
        asm volatile("cp.async.commit_group;" ::: "memory");
    };

    ull acc2[8][4];
#pragma unroll
    for (int i = 0; i < 8; i++)
#pragma unroll
        for (int j = 0; j < 4; j++) acc2[i][j] = 0ull;

    load_stage(0, 0);
#pragma unroll 1
    for (int it = 0; it < 16; ++it) {
        const int cur = it & 1;
        if (it < 15) load_stage(cur ^ 1, (it + 1) * 16);
        if (it < 15) asm volatile("cp.async.wait_group 1;" ::: "memory");
        else         asm volatile("cp.async.wait_group 0;" ::: "memory");
        __syncthreads();
#pragma unroll
        for (int k = 0; k < 16; k++) {
            float4 a0 = *reinterpret_cast<const float4*>(&As[cur][k][ty * 8]);
            float4 a1 = *reinterpret_cast<const float4*>(&As[cur][k][ty * 8 + 4]);
            ulonglong2 bb0 = *reinterpret_cast<const ulonglong2*>(&Bs[cur][k][tx * 8]);
            ulonglong2 bb1 = *reinterpret_cast<const ulonglong2*>(&Bs[cur][k][tx * 8 + 4]);
            ull b2[4] = { bb0.x, bb0.y, bb1.x, bb1.y };
            float av[8] = { a0.x, a0.y, a0.z, a0.w, a1.x, a1.y, a1.z, a1.w };
#pragma unroll
            for (int i = 0; i < 8; i++) {
                ull ap = pack2(av[i], av[i]);
#pragma unroll
                for (int j = 0; j < 4; j++) ffma2(acc2[i][j], ap, b2[j]);
            }
        }
        __syncthreads();
    }

    // epilogue: add bias, contiguous float4 stores
    float bv[8];
#pragma unroll
    for (int j = 0; j < 8; j++) bv[j] = bias[n0 + tx * 8 + j];
#pragma unroll
    for (int i = 0; i < 8; i++) {
        int m = m0 + ty * 8 + i;
        float2 e0 = unpack2(acc2[i][0]);
        float2 e1 = unpack2(acc2[i][1]);
        float2 e2 = unpack2(acc2[i][2]);
        float2 e3 = unpack2(acc2[i][3]);
        float4 o0, o1;
        o0.x = e0.x + bv[0]; o0.y = e0.y + bv[1];
        o0.z = e1.x + bv[2]; o0.w = e1.y + bv[3];
        o1.x = e2.x + bv[4]; o1.y = e2.y + bv[5];
        o1.z = e3.x + bv[6]; o1.w = e3.y + bv[7];
        float* dst = Xout + (size_t)m * G4_ + n0 + tx * 8;
        *reinterpret_cast<float4*>(dst)     = o0;
        *reinterpret_cast<float4*>(dst + 4) = o1;
    }
}

// ---------------------------------------------------------------------------
// K3: persistent BiLSTM recurrence.  Grid = 128 CTAs (64 per dir), 512 thr.
//     R8 changes vs R7:
//       - barrier arrive = per-CTA flag store (st.release, zero contention,
//         non-blocking); poll = every warp loads all 64 flags (1 v2 ld/lane)
//         + __all_sync — no single-thread poll, no broadcast BAR chain.
//       - h loads L1-CACHED (plain ld); one __threadfence() (CCTL.IVALL on
//         sm_103a) per step after barrier detection invalidates stale L1
//         lines, so the rq-duplicate loads hit L1 instead of paying L2 twice.
//       - h stores remain st.cg so the producer's L1 never holds h lines.
// ---------------------------------------------------------------------------
__global__ __launch_bounds__(512, 1) void k_steps(const int* __restrict__ lens,
                                                  const float* __restrict__ Whh_f,
                                                  const float* __restrict__ Whh_b) {
    __shared__ float w_s[256][16];        // [k][row]  16 KB (transposed Whh slice)
    __shared__ float part_s[8][16][64];   // k-slice partial gates  32 KB

    const int tid = threadIdx.x;
    const int dir = blockIdx.x >> 6;
    const int cb  = blockIdx.x & 63;
    const int j0  = cb * 4;
    const float* __restrict__ Whh = dir ? Whh_b : Whh_f;
    const float* __restrict__ X   = g_X + (size_t)dir * S_ * B_ * G4_;

    {
        int row = tid >> 5;                 // 0..15 (= gate*4 + ch)
        int gg  = row >> 2, ch = row & 3;
        int grw = gg * H_ + j0 + ch;
        const float* src = Whh + (size_t)grw * H_ + (tid & 31) * 8;
#pragma unroll
        for (int u = 0; u < 8; u += 4) {
            float4 v = *reinterpret_cast<const float4*>(src + u);
            int k0 = (tid & 31) * 8 + u;
            w_s[k0 + 0][row] = v.x;
            w_s[k0 + 1][row] = v.y;
            w_s[k0 + 2][row] = v.z;
            w_s[k0 + 3][row] = v.w;
        }
    }

    const int ks = tid >> 6;           // k-slice 0..7 (32 k each)
    const int rq = (tid >> 4) & 3;     // row quad 0..3
    const int bq = tid & 15;           // batch quad 0..15
    const int r0 = rq * 4;
    const int b0 = bq * 4;
    const int kbase = ks * 32;

    const bool pw  = (tid < 256);
    const int  pch = tid >> 6;         // 0..3 channel within CTA (valid when pw)
    const int  pb  = tid & 63;         // batch
    const int  Lp  = pw ? __ldg(lens + pb) : 0;
    float creg = 0.0f;

    const int lane = tid & 31;
    const int* flbase = &g_flag[dir][0];
    int* myflag = &g_flag[dir][cb];

    float* __restrict__ houtB = g_h + (size_t)dir * S_ * B_ * H_;

    float xg0 = 0.f, xg1 = 0.f, xg2 = 0.f, xg3 = 0.f;
    if (pw) {
        int m;
        if (dir == 0) m = pb;
        else { int rr = (0 < Lp) ? (Lp - 1) : 0; m = rr * B_ + pb; }
        const float* Xm = X + (size_t)m * G4_ + j0 + pch;
        xg0 = Xm[0 * H_]; xg1 = Xm[1 * H_]; xg2 = Xm[2 * H_]; xg3 = Xm[3 * H_];
    }
    __syncthreads();   // w_s ready

    for (int t = 0; t < S_; ++t) {
        if (t > 0) {
            // ---- wait for all 64 producer CTAs to reach step t ----
            {
                int guard = 1 << 18;
                int v0, v1;
                do {
                    asm volatile("ld.acquire.gpu.global.v2.s32 {%0, %1}, [%2];"
                                 : "=r"(v0), "=r"(v1) : "l"(flbase + 2 * lane) : "memory");
                } while (!__all_sync(0xffffffffu, (v0 >= t) & (v1 >= t)) && --guard);
            }
            __syncthreads();
            if (tid == 0) __threadfence();   // CCTL.IVALL: drop stale L1 h lines
            __syncthreads();

            ull a00 = 0, a01 = 0, a10 = 0, a11 = 0, a20 = 0, a21 = 0, a30 = 0, a31 = 0;
            const float* hsrc = &g_hT[dir][(t - 1) & 1][0][0] + (size_t)kbase * 64 + b0;
#pragma unroll 8
            for (int kk = 0; kk < 32; ++kk) {
                ulonglong2 h2 = *reinterpret_cast<const ulonglong2*>(hsrc + kk * 64);
                float4 wv = *reinterpret_cast<const float4*>(&w_s[kbase + kk][r0]);
                ull w0 = pack2(wv.x, wv.x), w1 = pack2(wv.y, wv.y);
                ull w2 = pack2(wv.z, wv.z), w3 = pack2(wv.w, wv.w);
                ffma2(a00, w0, h2.x); ffma2(a01, w0, h2.y);
                ffma2(a10, w1, h2.x); ffma2(a11, w1, h2.y);
                ffma2(a20, w2, h2.x); ffma2(a21, w2, h2.y);
                ffma2(a30, w3, h2.x); ffma2(a31, w3, h2.y);
            }
            float2 l0 = unpack2(a00), h0 = unpack2(a01);
            float2 l1 = unpack2(a10), h1 = unpack2(a11);
            float2 l2 = unpack2(a20), h2v = unpack2(a21);
            float2 l3 = unpack2(a30), h3 = unpack2(a31);
            *reinterpret_cast<float4*>(&part_s[ks][r0 + 0][b0]) = make_float4(l0.x, l0.y, h0.x, h0.y);
            *reinterpret_cast<float4*>(&part_s[ks][r0 + 1][b0]) = make_float4(l1.x, l1.y, h1.x, h1.y);
            *reinterpret_cast<float4*>(&part_s[ks][r0 + 2][b0]) = make_float4(l2.x, l2.y, h2v.x, h2v.y);
            *reinterpret_cast<float4*>(&part_s[ks][r0 + 3][b0]) = make_float4(l3.x, l3.y, h3.x, h3.y);
            __syncthreads();
        }

        if (pw) {
            float gv0 = xg0, gv1 = xg1, gv2 = xg2, gv3 = xg3;
            if (t > 0) {
#pragma unroll
                for (int s = 0; s < 8; ++s) {
                    gv0 += part_s[s][0 * 4 + pch][pb];
                    gv1 += part_s[s][1 * 4 + pch][pb];
                    gv2 += part_s[s][2 * 4 + pch][pb];
                    gv3 += part_s[s][3 * 4 + pch][pb];
                }
            }
            float cn = fsig(gv1) * creg + fsig(gv0) * ftanh(gv2);
            float hn = fsig(gv3) * ftanh(cn);
            creg = cn;
            houtB[(size_t)t * B_ * H_ + pb * H_ + j0 + pch] = hn;
            stcg32(&g_hT[dir][t & 1][j0 + pch][pb], hn);
        }

        if (t < S_ - 1) {
            __syncthreads();                 // h(t) stores done CTA-wide
            // non-blocking arrive: flag := t+1 (release orders the h stores)
            if (tid == 0)
                asm volatile("st.release.gpu.global.s32 [%0], %1;" :: "l"(myflag), "r"(t + 1) : "memory");

            // X(t+1) prefetch — overlaps peers' arrival
            if (pw) {
                int tn = t + 1;
                int m;
                if (dir == 0) m = tn * B_ + pb;
                else { int rr = (tn < Lp) ? (Lp - 1 - tn) : tn; m = rr * B_ + pb; }
                const float* Xm = X + (size_t)m * G4_ + j0 + pch;
                xg0 = Xm[0 * H_]; xg1 = Xm[1 * H_]; xg2 = Xm[2 * H_]; xg3 = Xm[3 * H_];
            }
        }
    }
}

// ---------------------------------------------------------------------------
// K4: u/w projections.  Block = (b, s-group of 8), 512 threads.
// ---------------------------------------------------------------------------
__global__ __launch_bounds__(512) void k_uw(const int* __restrict__ lens,
                                            const float* __restrict__ Ua,
                                            const float* __restrict__ Wa) {
    __shared__ float enc_s[8][516];

    const int b  = blockIdx.x;
    const int sg = blockIdx.y;
    const int tid = threadIdx.x;
    const int L = lens[b];

    {
        int lr = tid >> 6;             // local s row 0..7
        int lc = (tid & 63) * 8;       // col 0..504 step 8
        int s_row = sg * 8 + lr;
        bool valid = (s_row < L);
        int ridx = valid ? (L - 1 - s_row) : s_row;
        const float* src = (lc < 256)
            ? g_h + (size_t)s_row * B_ * H_ + b * H_ + lc
            : g_h + (size_t)S_ * B_ * H_ + (size_t)ridx * B_ * H_ + b * H_ + (lc - 256);
        float4 v0 = make_float4(0.f, 0.f, 0.f, 0.f);
        float4 v1 = v0;
        if (valid) {
            v0 = *reinterpret_cast<const float4*>(src);
            v1 = *reinterpret_cast<const float4*>(src + 4);
        }
        *reinterpret_cast<float4*>(&enc_s[lr][lc])     = v0;
        *reinterpret_cast<float4*>(&enc_s[lr][lc + 4]) = v1;
    }
    __syncthreads();

    const int row = tid >> 3;
    const int sl  = tid & 7;
    if (row < 2 * HID_) {
        const float* __restrict__ Wrow =
            (row < HID_) ? (Ua + (size_t)row * 2 * H_) : (Wa + (size_t)(row - HID_) * 2 * H_);
        float acc = 0.f;
#pragma unroll 8
        for (int k = 0; k < 2 * H_; k += 4) {
            float4 wv = *reinterpret_cast<const float4*>(Wrow + k);
            float4 ev = *reinterpret_cast<const float4*>(&enc_s[sl][k]);
            acc += wv.x * ev.x + wv.y * ev.y + wv.z * ev.z + wv.w * ev.w;
        }
        int s = sg * 8 + sl;
        if (row < HID_)
            g_U[((size_t)b * S_ + s) * HID_ + row] = acc;
        else
            g_Wt[(size_t)b * HID_ * S_ + (size_t)(row - HID_) * S_ + s] = acc;
    }
}

// ---------------------------------------------------------------------------
// K5: scores + predictions (MUFU tanh).
// ---------------------------------------------------------------------------
__global__ void k_scores(const float* __restrict__ va, float* __restrict__ out) {
    const int i = blockIdx.x;
    const int b = blockIdx.y;
    const int j = threadIdx.x;   // 128

    __shared__ float u_s[HID_];
    __shared__ float va_s[HID_];
    if (j < HID_) {
        u_s[j]  = g_U[((size_t)b * S_ + i) * HID_ + j];
        va_s[j] = va[j];
    }
    __syncthreads();

    const float* __restrict__ Wb = g_Wt + (size_t)b * HID_ * S_;
    float acc = 0.f;
#pragma unroll
    for (int k = 0; k < HID_; k++) {
        float wv = Wb[k * S_ + j];
        acc += ftanh(u_s[k] + wv) * va_s[k];
    }
    size_t idx = ((size_t)b * S_ + i) * S_ + j;
    out[idx] = acc;
    out[(size_t)B_ * S_ * S_ + idx] = (acc >= 0.0f) ? 1.0f : 0.0f;
}

// ---------------------------------------------------------------------------
extern "C" void kernel_launch(void* const* d_in, const int* in_sizes, int n_in,
                              void* d_out, int out_size) {
    const int*   concepts = (const int*)d_in[0];
    const int*   lens     = (const int*)d_in[1];
    const float* emb      = (const float*)d_in[2];
    const float* Wih_f    = (const float*)d_in[3];
    const float* Whh_f    = (const float*)d_in[4];
    const float* b_f      = (const float*)d_in[5];
    const float* Wih_b    = (const float*)d_in[6];
    const float* Whh_b    = (const float*)d_in[7];
    const float* b_b      = (const float*)d_in[8];
    const float* Ua       = (const float*)d_in[9];
    const float* Wa       = (const float*)d_in[10];
    const float* va       = (const float*)d_in[11];
    float* out = (float*)d_out;

    float* embT_p = nullptr;
    float* WihT_p = nullptr;
    float* emb_p  = nullptr;
    cudaGetSymbolAddress((void**)&embT_p, g_embT);
    cudaGetSymbolAddress((void**)&WihT_p, g_WihT);
    cudaGetSymbolAddress((void**)&emb_p,  g_emb);

    k_gather<<<S_ * B_, 64>>>(concepts, emb);
    k_transpose<<<dim3(E_ / 32, (S_ * B_) / 32), dim3(32, 8)>>>(emb_p, embT_p, S_ * B_, E_);
    k_transpose<<<dim3(E_ / 32, G4_ / 32), dim3(32, 8)>>>(Wih_f, WihT_p, G4_, E_);
    k_transpose<<<dim3(E_ / 32, G4_ / 32), dim3(32, 8)>>>(Wih_b, WihT_p + E_ * G4_, G4_, E_);
    k_xgemm<<<dim3(64, 8, 2), 256>>>(b_f, b_b);
    k_zero_bar<<<1, 256>>>();
    k_steps<<<2 * NCTA_DIR, 512>>>(lens, Whh_f, Whh_b);
    k_uw<<<dim3(B_, S_ / 8), 512>>>(lens, Ua, Wa);
    k_scores<<<dim3(S_, B_), 128>>>(va, out);
}

// round 9
// speedup vs baseline: 2.2182x; 2.2182x over previous
#include <cuda_runtime.h>
#include <math.h>
#include <stdint.h>

typedef unsigned long long ull;

// Problem constants
constexpr int S_   = 128;   // sequence length
constexpr int B_   = 64;    // batch
constexpr int E_   = 256;   // embedding dim
constexpr int H_   = 256;   // hidden
constexpr int G4_  = 1024;  // 4*H (gates)
constexpr int HID_ = 30;    // attention hidden
constexpr int NCTA_DIR = 64;   // CTAs per direction in persistent step kernel

// Scratch (static device globals — no runtime allocation)
__device__ float g_emb[S_ * B_ * E_];        // (t,b,e)
__device__ float g_embT[E_ * S_ * B_];       // transposed: [e][t*B+b]
__device__ float g_WihT[2 * E_ * G4_];       // transposed Wih per dir: [k][n]
__device__ float g_X[2 * S_ * B_ * G4_];     // x-projections per dir, bias folded in
__device__ float g_h[2 * S_ * B_ * H_];      // [dir][t][b][k]  (for K4)
__device__ float g_hT[2][2][H_][B_];         // ping-pong [dir][parity][k][b]
__device__ int   g_flag[2][NCTA_DIR];        // per-CTA progress flags (monotone step count)
__device__ float g_U[B_ * S_ * HID_];        // u = enc @ Ua^T
__device__ float g_Wt[B_ * HID_ * S_];       // w transposed: [b][k][s]

// fast activations: MUFU-based, rel err ~2e-7 (budget is 1e-3)
__device__ __forceinline__ float fsig(float x)  { return 1.0f / (1.0f + __expf(-x)); }
__device__ __forceinline__ float ftanh(float x) { return 2.0f / (1.0f + __expf(-2.0f * x)) - 1.0f; }

// pure (non-volatile) packed fp32 math — scheduler may move these freely
__device__ __forceinline__ void ffma2(ull& d, ull a, ull b) {
    asm("fma.rn.f32x2 %0, %1, %2, %0;" : "+l"(d) : "l"(a), "l"(b));
}
__device__ __forceinline__ ull pack2(float lo, float hi) {
    ull r; asm("mov.b64 %0, {%1, %2};" : "=l"(r) : "f"(lo), "f"(hi)); return r;
}
__device__ __forceinline__ float2 unpack2(ull v) {
    float2 r; asm("mov.b64 {%0, %1}, %2;" : "=f"(r.x), "=f"(r.y) : "l"(v)); return r;
}
// L1-bypassing 16B load (h produced by other CTAs within this launch)
__device__ __forceinline__ void ldcg128(ull& x, ull& y, const float* p) {
    asm volatile("ld.global.cg.v2.u64 {%0, %1}, [%2];" : "=l"(x), "=l"(y) : "l"(p));
}
__device__ __forceinline__ void stcg32(float* p, float v) {
    asm volatile("st.global.cg.f32 [%0], %1;" :: "l"(p), "f"(v));
}
__device__ __forceinline__ void cp16(uint32_t smem_dst, const void* gsrc) {
    asm volatile("cp.async.cg.shared.global [%0], [%1], 16;" :: "r"(smem_dst), "l"(gsrc) : "memory");
}

// ---------------------------------------------------------------------------
// K0: zero the progress flags (stream-ordered before k_steps)
// ---------------------------------------------------------------------------
__global__ void k_zero_bar() {
    if (threadIdx.x < 2 * NCTA_DIR) (&g_flag[0][0])[threadIdx.x] = 0;
}

// ---------------------------------------------------------------------------
// K1: embedding gather.  grid = S*B blocks, 64 threads (float4 row copy)
// ---------------------------------------------------------------------------
__global__ void k_gather(const int* __restrict__ concepts,
                         const float* __restrict__ table) {
    int tb  = blockIdx.x;                      // t*B + b
    int tok = concepts[tb];
    const float4* src = reinterpret_cast<const float4*>(table + (size_t)tok * E_);
    float4*       dst = reinterpret_cast<float4*>(g_emb + (size_t)tb * E_);
    dst[threadIdx.x] = src[threadIdx.x];
}

// ---------------------------------------------------------------------------
// K1b: tiled transpose  src[M][N] -> dst[N][M]   (M,N multiples of 32)
// ---------------------------------------------------------------------------
__global__ void k_transpose(const float* __restrict__ src, float* __restrict__ dst,
                            int M, int N) {
    __shared__ float t[32][33];
    int nb = blockIdx.x * 32, mb = blockIdx.y * 32;
    int tx = threadIdx.x, ty = threadIdx.y;   // (32, 8)
#pragma unroll
    for (int i = 0; i < 4; i++)
        t[ty + i * 8][tx] = src[(size_t)(mb + ty + i * 8) * N + nb + tx];
    __syncthreads();
#pragma unroll
    for (int i = 0; i < 4; i++)
        dst[(size_t)(nb + ty + i * 8) * M + mb + tx] = t[tx][ty + i * 8];
}

// ---------------------------------------------------------------------------
// K2: x-projection GEMM  X[dir] = emb @ Wih[dir]^T + b[dir]
//     M=8192, N=1024, K=256.  BM=BN=128, BK=16, 256 thr, 8x8 microtile,
//     packed f32x2 FMA.  Sources pre-transposed (g_embT / g_WihT) so tiles
//     load k-major directly via cp.async; 2-stage double buffer.
// ---------------------------------------------------------------------------
__global__ __launch_bounds__(256) void k_xgemm(const float* __restrict__ b_f,
                                               const float* __restrict__ b_b) {
    const int dir = blockIdx.z;
    const float* __restrict__ AT   = g_embT;                      // [k][8192]
    const float* __restrict__ BT   = g_WihT + (size_t)dir * E_ * G4_;  // [k][1024]
    const float* __restrict__ bias = dir ? b_b : b_f;
    float* __restrict__ Xout = g_X + (size_t)dir * S_ * B_ * G4_;

    __shared__ float As[2][16][132];   // [stage][k][m]
    __shared__ float Bs[2][16][132];   // [stage][k][n]

    const int m0  = blockIdx.x * 128;
    const int n0  = blockIdx.y * 128;
    const int tid = threadIdx.x;
    const int tx  = tid & 15;       // -> n
    const int ty  = tid >> 4;       // -> m

    const uint32_t as_sa = (uint32_t)__cvta_generic_to_shared(&As[0][0][0]);
    const uint32_t bs_sa = (uint32_t)__cvta_generic_to_shared(&Bs[0][0][0]);
    const int q0 = tid * 2;
    const int r0q = q0 >> 5, c0q = (q0 & 31) * 4;        // quad 0: row, col4
    const int r1q = (q0 + 1) >> 5, c1q = ((q0 + 1) & 31) * 4;

    auto load_stage = [&](int st, int kc) {
        uint32_t abase = as_sa + st * (16 * 132 * 4);
        uint32_t bbase = bs_sa + st * (16 * 132 * 4);
        cp16(abase + (r0q * 132 + c0q) * 4, AT + (size_t)(kc + r0q) * 8192 + m0 + c0q);
        cp16(abase + (r1q * 132 + c1q) * 4, AT + (size_t)(kc + r1q) * 8192 + m0 + c1q);
        cp16(bbase + (r0q * 132 + c0q) * 4, BT + (size_t)(kc + r0q) * 1024 + n0 + c0q);
        cp16(bbase + (r1q * 132 + c1q) * 4, BT + (size_t)(kc + r1q) * 1024 + n0 + c1q);
        asm volatile("cp.async.commit_group;" ::: "memory");
    };

    ull acc2[8][4];
#pragma unroll
    for (int i = 0; i < 8; i++)
#pragma unroll
        for (int j = 0; j < 4; j++) acc2[i][j] = 0ull;

    load_stage(0, 0);
#pragma unroll 1
    for (int it = 0; it < 16; ++it) {
        const int cur = it & 1;
        if (it < 15) load_stage(cur ^ 1, (it + 1) * 16);
        if (it < 15) asm volatile("cp.async.wait_group 1;" ::: "memory");
        else         asm volatile("cp.async.wait_group 0;" ::: "memory");
        __syncthreads();
#pragma unroll
        for (int k = 0; k < 16; k++) {
            float4 a0 = *reinterpret_cast<const float4*>(&As[cur][k][ty * 8]);
            float4 a1 = *reinterpret_cast<const float4*>(&As[cur][k][ty * 8 + 4]);
            ulonglong2 bb0 = *reinterpret_cast<const ulonglong2*>(&Bs[cur][k][tx * 8]);
            ulonglong2 bb1 = *reinterpret_cast<const ulonglong2*>(&Bs[cur][k][tx * 8 + 4]);
            ull b2[4] = { bb0.x, bb0.y, bb1.x, bb1.y };
            float av[8] = { a0.x, a0.y, a0.z, a0.w, a1.x, a1.y, a1.z, a1.w };
#pragma unroll
            for (int i = 0; i < 8; i++) {
                ull ap = pack2(av[i], av[i]);
#pragma unroll
                for (int j = 0; j < 4; j++) ffma2(acc2[i][j], ap, b2[j]);
            }
        }
        __syncthreads();
    }

    // epilogue: add bias, contiguous float4 stores
    float bv[8];
#pragma unroll
    for (int j = 0; j < 8; j++) bv[j] = bias[n0 + tx * 8 + j];
#pragma unroll
    for (int i = 0; i < 8; i++) {
        int m = m0 + ty * 8 + i;
        float2 e0 = unpack2(acc2[i][0]);
        float2 e1 = unpack2(acc2[i][1]);
        float2 e2 = unpack2(acc2[i][2]);
        float2 e3 = unpack2(acc2[i][3]);
        float4 o0, o1;
        o0.x = e0.x + bv[0]; o0.y = e0.y + bv[1];
        o0.z = e1.x + bv[2]; o0.w = e1.y + bv[3];
        o1.x = e2.x + bv[4]; o1.y = e2.y + bv[5];
        o1.z = e3.x + bv[6]; o1.w = e3.y + bv[7];
        float* dst = Xout + (size_t)m * G4_ + n0 + tx * 8;
        *reinterpret_cast<float4*>(dst)     = o0;
        *reinterpret_cast<float4*>(dst + 4) = o1;
    }
}

// ---------------------------------------------------------------------------
// K3: persistent BiLSTM recurrence.  Grid = 128 CTAs (64 per dir), 512 thr.
//     == R7 structure (proven 516us) with ONE change: the barrier.
//       arrive: per-CTA flag st.release (zero contention, non-blocking)
//       wait:   WARP 0 ONLY polls all 64 flags (one v2 ld per lane) then
//               releases the CTA via __syncthreads.  No 64-way ATOMG
//               serialization, no all-warp poll storm.
//     h path unchanged from R7: ld.cg loads, st.cg stores.
// ---------------------------------------------------------------------------
__global__ __launch_bounds__(512, 1) void k_steps(const int* __restrict__ lens,
                                                  const float* __restrict__ Whh_f,
                                                  const float* __restrict__ Whh_b) {
    __shared__ float w_s[256][16];        // [k][row]  16 KB (transposed Whh slice)
    __shared__ float part_s[8][16][64];   // k-slice partial gates  32 KB

    const int tid = threadIdx.x;
    const int dir = blockIdx.x >> 6;
    const int cb  = blockIdx.x & 63;
    const int j0  = cb * 4;
    const float* __restrict__ Whh = dir ? Whh_b : Whh_f;
    const float* __restrict__ X   = g_X + (size_t)dir * S_ * B_ * G4_;

    {
        int row = tid >> 5;                 // 0..15 (= gate*4 + ch)
        int gg  = row >> 2, ch = row & 3;
        int grw = gg * H_ + j0 + ch;
        const float* src = Whh + (size_t)grw * H_ + (tid & 31) * 8;
#pragma unroll
        for (int u = 0; u < 8; u += 4) {
            float4 v = *reinterpret_cast<const float4*>(src + u);
            int k0 = (tid & 31) * 8 + u;
            w_s[k0 + 0][row] = v.x;
            w_s[k0 + 1][row] = v.y;
            w_s[k0 + 2][row] = v.z;
            w_s[k0 + 3][row] = v.w;
        }
    }

    const int ks = tid >> 6;           // k-slice 0..7 (32 k each)
    const int rq = (tid >> 4) & 3;     // row quad 0..3
    const int bq = tid & 15;           // batch quad 0..15
    const int r0 = rq * 4;
    const int b0 = bq * 4;
    const int kbase = ks * 32;

    const bool pw  = (tid < 256);
    const int  pch = tid >> 6;         // 0..3 channel within CTA (valid when pw)
    const int  pb  = tid & 63;         // batch
    const int  Lp  = pw ? __ldg(lens + pb) : 0;
    float creg = 0.0f;

    const int lane = tid & 31;
    const int* flbase = &g_flag[dir][0];
    int* myflag = &g_flag[dir][cb];

    float* __restrict__ houtB = g_h + (size_t)dir * S_ * B_ * H_;

    float xg0 = 0.f, xg1 = 0.f, xg2 = 0.f, xg3 = 0.f;
    if (pw) {
        int m;
        if (dir == 0) m = pb;
        else { int rr = (0 < Lp) ? (Lp - 1) : 0; m = rr * B_ + pb; }
        const float* Xm = X + (size_t)m * G4_ + j0 + pch;
        xg0 = Xm[0 * H_]; xg1 = Xm[1 * H_]; xg2 = Xm[2 * H_]; xg3 = Xm[3 * H_];
    }
    __syncthreads();   // w_s ready

    for (int t = 0; t < S_; ++t) {
        if (t > 0) {
            // ---- wait: WARP 0 ONLY polls the 64 producer flags ----
            if (tid < 32) {
                int guard = 1 << 18;
                int v0, v1;
                do {
                    asm volatile("ld.acquire.gpu.global.v2.s32 {%0, %1}, [%2];"
                                 : "=r"(v0), "=r"(v1) : "l"(flbase + 2 * lane) : "memory");
                } while (!__all_sync(0xffffffffu, (v0 >= t) & (v1 >= t)) && --guard);
            }
            __syncthreads();

            ull a00 = 0, a01 = 0, a10 = 0, a11 = 0, a20 = 0, a21 = 0, a30 = 0, a31 = 0;
            const float* hsrc = &g_hT[dir][(t - 1) & 1][0][0] + (size_t)kbase * 64 + b0;
#pragma unroll 8
            for (int kk = 0; kk < 32; ++kk) {
                ull hx, hy;
                ldcg128(hx, hy, hsrc + kk * 64);
                float4 wv = *reinterpret_cast<const float4*>(&w_s[kbase + kk][r0]);
                ull w0 = pack2(wv.x, wv.x), w1 = pack2(wv.y, wv.y);
                ull w2 = pack2(wv.z, wv.z), w3 = pack2(wv.w, wv.w);
                ffma2(a00, w0, hx); ffma2(a01, w0, hy);
                ffma2(a10, w1, hx); ffma2(a11, w1, hy);
                ffma2(a20, w2, hx); ffma2(a21, w2, hy);
                ffma2(a30, w3, hx); ffma2(a31, w3, hy);
            }
            float2 l0 = unpack2(a00), h0 = unpack2(a01);
            float2 l1 = unpack2(a10), h1 = unpack2(a11);
            float2 l2 = unpack2(a20), h2v = unpack2(a21);
            float2 l3 = unpack2(a30), h3 = unpack2(a31);
            *reinterpret_cast<float4*>(&part_s[ks][r0 + 0][b0]) = make_float4(l0.x, l0.y, h0.x, h0.y);
            *reinterpret_cast<float4*>(&part_s[ks][r0 + 1][b0]) = make_float4(l1.x, l1.y, h1.x, h1.y);
            *reinterpret_cast<float4*>(&part_s[ks][r0 + 2][b0]) = make_float4(l2.x, l2.y, h2v.x, h2v.y);
            *reinterpret_cast<float4*>(&part_s[ks][r0 + 3][b0]) = make_float4(l3.x, l3.y, h3.x, h3.y);
            __syncthreads();
        }

        if (pw) {
            float gv0 = xg0, gv1 = xg1, gv2 = xg2, gv3 = xg3;
            if (t > 0) {
#pragma unroll
                for (int s = 0; s < 8; ++s) {
                    gv0 += part_s[s][0 * 4 + pch][pb];
                    gv1 += part_s[s][1 * 4 + pch][pb];
                    gv2 += part_s[s][2 * 4 + pch][pb];
                    gv3 += part_s[s][3 * 4 + pch][pb];
                }
            }
            float cn = fsig(gv1) * creg + fsig(gv0) * ftanh(gv2);
            float hn = fsig(gv3) * ftanh(cn);
            creg = cn;
            houtB[(size_t)t * B_ * H_ + pb * H_ + j0 + pch] = hn;
            stcg32(&g_hT[dir][t & 1][j0 + pch][pb], hn);
        }

        if (t < S_ - 1) {
            __syncthreads();                 // h(t) stores done CTA-wide
            // non-blocking arrive: flag := t+1 (release orders the h stores)
            if (tid == 0)
                asm volatile("st.release.gpu.global.s32 [%0], %1;" :: "l"(myflag), "r"(t + 1) : "memory");

            // X(t+1) prefetch — overlaps peers' arrival
            if (pw) {
                int tn = t + 1;
                int m;
                if (dir == 0) m = tn * B_ + pb;
                else { int rr = (tn < Lp) ? (Lp - 1 - tn) : tn; m = rr * B_ + pb; }
                const float* Xm = X + (size_t)m * G4_ + j0 + pch;
                xg0 = Xm[0 * H_]; xg1 = Xm[1 * H_]; xg2 = Xm[2 * H_]; xg3 = Xm[3 * H_];
            }
        }
    }
}

// ---------------------------------------------------------------------------
// K4: u/w projections.  Block = (b, s-group of 8), 512 threads.
// ---------------------------------------------------------------------------
__global__ __launch_bounds__(512) void k_uw(const int* __restrict__ lens,
                                            const float* __restrict__ Ua,
                                            const float* __restrict__ Wa) {
    __shared__ float enc_s[8][516];

    const int b  = blockIdx.x;
    const int sg = blockIdx.y;
    const int tid = threadIdx.x;
    const int L = lens[b];

    {
        int lr = tid >> 6;             // local s row 0..7
        int lc = (tid & 63) * 8;       // col 0..504 step 8
        int s_row = sg * 8 + lr;
        bool valid = (s_row < L);
        int ridx = valid ? (L - 1 - s_row) : s_row;
        const float* src = (lc < 256)
            ? g_h + (size_t)s_row * B_ * H_ + b * H_ + lc
            : g_h + (size_t)S_ * B_ * H_ + (size_t)ridx * B_ * H_ + b * H_ + (lc - 256);
        float4 v0 = make_float4(0.f, 0.f, 0.f, 0.f);
        float4 v1 = v0;
        if (valid) {
            v0 = *reinterpret_cast<const float4*>(src);
            v1 = *reinterpret_cast<const float4*>(src + 4);
        }
        *reinterpret_cast<float4*>(&enc_s[lr][lc])     = v0;
        *reinterpret_cast<float4*>(&enc_s[lr][lc + 4]) = v1;
    }
    __syncthreads();

    const int row = tid >> 3;
    const int sl  = tid & 7;
    if (row < 2 * HID_) {
        const float* __restrict__ Wrow =
            (row < HID_) ? (Ua + (size_t)row * 2 * H_) : (Wa + (size_t)(row - HID_) * 2 * H_);
        float acc = 0.f;
#pragma unroll 8
        for (int k = 0; k < 2 * H_; k += 4) {
            float4 wv = *reinterpret_cast<const float4*>(Wrow + k);
            float4 ev = *reinterpret_cast<const float4*>(&enc_s[sl][k]);
            acc += wv.x * ev.x + wv.y * ev.y + wv.z * ev.z + wv.w * ev.w;
        }
        int s = sg * 8 + sl;
        if (row < HID_)
            g_U[((size_t)b * S_ + s) * HID_ + row] = acc;
        else
            g_Wt[(size_t)b * HID_ * S_ + (size_t)(row - HID_) * S_ + s] = acc;
    }
}

// ---------------------------------------------------------------------------
// K5: scores + predictions (MUFU tanh).
// ---------------------------------------------------------------------------
__global__ void k_scores(const float* __restrict__ va, float* __restrict__ out) {
    const int i = blockIdx.x;
    const int b = blockIdx.y;
    const int j = threadIdx.x;   // 128

    __shared__ float u_s[HID_];
    __shared__ float va_s[HID_];
    if (j < HID_) {
        u_s[j]  = g_U[((size_t)b * S_ + i) * HID_ + j];
        va_s[j] = va[j];
    }
    __syncthreads();

    const float* __restrict__ Wb = g_Wt + (size_t)b * HID_ * S_;
    float acc = 0.f;
#pragma unroll
    for (int k = 0; k < HID_; k++) {
        float wv = Wb[k * S_ + j];
        acc += ftanh(u_s[k] + wv) * va_s[k];
    }
    size_t idx = ((size_t)b * S_ + i) * S_ + j;
    out[idx] = acc;
    out[(size_t)B_ * S_ * S_ + idx] = (acc >= 0.0f) ? 1.0f : 0.0f;
}

// ---------------------------------------------------------------------------
extern "C" void kernel_launch(void* const* d_in, const int* in_sizes, int n_in,
                              void* d_out, int out_size) {
    const int*   concepts = (const int*)d_in[0];
    const int*   lens     = (const int*)d_in[1];
    const float* emb      = (const float*)d_in[2];
    const float* Wih_f    = (const float*)d_in[3];
    const float* Whh_f    = (const float*)d_in[4];
    const float* b_f      = (const float*)d_in[5];
    const float* Wih_b    = (const float*)d_in[6];
    const float* Whh_b    = (const float*)d_in[7];
    const float* b_b      = (const float*)d_in[8];
    const float* Ua       = (const float*)d_in[9];
    const float* Wa       = (const float*)d_in[10];
    const float* va       = (const float*)d_in[11];
    float* out = (float*)d_out;

    float* embT_p = nullptr;
    float* WihT_p = nullptr;
    float* emb_p  = nullptr;
    cudaGetSymbolAddress((void**)&embT_p, g_embT);
    cudaGetSymbolAddress((void**)&WihT_p, g_WihT);
    cudaGetSymbolAddress((void**)&emb_p,  g_emb);

    k_gather<<<S_ * B_, 64>>>(concepts, emb);
    k_transpose<<<dim3(E_ / 32, (S_ * B_) / 32), dim3(32, 8)>>>(emb_p, embT_p, S_ * B_, E_);
    k_transpose<<<dim3(E_ / 32, G4_ / 32), dim3(32, 8)>>>(Wih_f, WihT_p, G4_, E_);
    k_transpose<<<dim3(E_ / 32, G4_ / 32), dim3(32, 8)>>>(Wih_b, WihT_p + E_ * G4_, G4_, E_);
    k_xgemm<<<dim3(64, 8, 2), 256>>>(b_f, b_b);
    k_zero_bar<<<1, 256>>>();
    k_steps<<<2 * NCTA_DIR, 512>>>(lens, Whh_f, Whh_b);
    k_uw<<<dim3(B_, S_ / 8), 512>>>(lens, Ua, Wa);
    k_scores<<<dim3(S_, B_), 128>>>(va, out);
}

// round 10
// speedup vs baseline: 2.8907x; 1.3032x over previous
#include <cuda_runtime.h>
#include <math.h>
#include <stdint.h>

typedef unsigned long long ull;

// Problem constants
constexpr int S_   = 128;   // sequence length
constexpr int B_   = 64;    // batch
constexpr int E_   = 256;   // embedding dim
constexpr int H_   = 256;   // hidden
constexpr int G4_  = 1024;  // 4*H (gates)
constexpr int HID_ = 30;    // attention hidden
constexpr int NCTA_DIR = 64;   // CTAs per direction in persistent step kernel

// Scratch (static device globals — no runtime allocation)
__device__ float g_emb[S_ * B_ * E_];        // (t,b,e)
__device__ float g_embT[E_ * S_ * B_];       // transposed: [e][t*B+b]
__device__ float g_WihT[2 * E_ * G4_];       // transposed Wih per dir: [k][n]
__device__ float g_X[2 * S_ * B_ * G4_];     // x-projections per dir, bias folded in
__device__ float g_h[2 * S_ * B_ * H_];      // [dir][t][b][k]  (for K4)
__device__ float g_hT[2][2][H_][B_];         // ping-pong [dir][parity][k][b]
__device__ int   g_bar[2 * S_];              // grid-barrier arrival counters
__device__ float g_U[B_ * S_ * HID_];        // u = enc @ Ua^T
__device__ float g_Wt[B_ * HID_ * S_];       // w transposed: [b][k][s]

// fast activations: MUFU-based, rel err ~2e-7 (budget is 1e-3)
__device__ __forceinline__ float fsig(float x)  { return 1.0f / (1.0f + __expf(-x)); }
__device__ __forceinline__ float ftanh(float x) { return 2.0f / (1.0f + __expf(-2.0f * x)) - 1.0f; }

// pure (non-volatile) packed fp32 math — scheduler may move these freely
__device__ __forceinline__ void ffma2(ull& d, ull a, ull b) {
    asm("fma.rn.f32x2 %0, %1, %2, %0;" : "+l"(d) : "l"(a), "l"(b));
}
__device__ __forceinline__ ull pack2(float lo, float hi) {
    ull r; asm("mov.b64 %0, {%1, %2};" : "=l"(r) : "f"(lo), "f"(hi)); return r;
}
__device__ __forceinline__ float2 unpack2(ull v) {
    float2 r; asm("mov.b64 {%0, %1}, %2;" : "=f"(r.x), "=f"(r.y) : "l"(v)); return r;
}
// L1-bypassing 16B load (h produced by other CTAs within this launch)
__device__ __forceinline__ void ldcg128(ull& x, ull& y, const float* p) {
    asm volatile("ld.global.cg.v2.u64 {%0, %1}, [%2];" : "=l"(x), "=l"(y) : "l"(p));
}
__device__ __forceinline__ void stcg32(float* p, float v) {
    asm volatile("st.global.cg.f32 [%0], %1;" :: "l"(p), "f"(v));
}
__device__ __forceinline__ void cp16(uint32_t smem_dst, const void* gsrc) {
    asm volatile("cp.async.cg.shared.global [%0], [%1], 16;" :: "r"(smem_dst), "l"(gsrc) : "memory");
}

// ---------------------------------------------------------------------------
// K0: zero the grid-barrier counters (stream-ordered before k_steps)
// ---------------------------------------------------------------------------
__global__ void k_zero_bar() {
    if (threadIdx.x < 2 * S_) g_bar[threadIdx.x] = 0;
}

// ---------------------------------------------------------------------------
// K1: embedding gather.  grid = S*B blocks, 64 threads (float4 row copy)
// ---------------------------------------------------------------------------
__global__ void k_gather(const int* __restrict__ concepts,
                         const float* __restrict__ table) {
    int tb  = blockIdx.x;                      // t*B + b
    int tok = concepts[tb];
    const float4* src = reinterpret_cast<const float4*>(table + (size_t)tok * E_);
    float4*       dst = reinterpret_cast<float4*>(g_emb + (size_t)tb * E_);
    dst[threadIdx.x] = src[threadIdx.x];
}

// ---------------------------------------------------------------------------
// K1b: tiled transpose  src[M][N] -> dst[N][M]   (M,N multiples of 32)
// ---------------------------------------------------------------------------
__global__ void k_transpose(const float* __restrict__ src, float* __restrict__ dst,
                            int M, int N) {
    __shared__ float t[32][33];
    int nb = blockIdx.x * 32, mb = blockIdx.y * 32;
    int tx = threadIdx.x, ty = threadIdx.y;   // (32, 8)
#pragma unroll
    for (int i = 0; i < 4; i++)
        t[ty + i * 8][tx] = src[(size_t)(mb + ty + i * 8) * N + nb + tx];
    __syncthreads();
#pragma unroll
    for (int i = 0; i < 4; i++)
        dst[(size_t)(nb + ty + i * 8) * M + mb + tx] = t[tx][ty + i * 8];
}

// ---------------------------------------------------------------------------
// K2: x-projection GEMM  X[dir] = emb @ Wih[dir]^T + b[dir]
//     M=8192, N=1024, K=256.  BM=BN=128, BK=16, 256 thr, 8x8 microtile,
//     packed f32x2 FMA.  Sources pre-transposed (g_embT / g_WihT) so tiles
//     load k-major directly via cp.async; 2-stage double buffer.
// ---------------------------------------------------------------------------
__global__ __launch_bounds__(256) void k_xgemm(const float* __restrict__ b_f,
                                               const float* __restrict__ b_b) {
    const int dir = blockIdx.z;
    const float* __restrict__ AT   = g_embT;                      // [k][8192]
    const float* __restrict__ BT   = g_WihT + (size_t)dir * E_ * G4_;  // [k][1024]
    const float* __restrict__ bias = dir ? b_b : b_f;
    float* __restrict__ Xout = g_X + (size_t)dir * S_ * B_ * G4_;

    __shared__ float As[2][16][132];   // [stage][k][m]
    __shared__ float Bs[2][16][132];   // [stage][k][n]

    const int m0  = blockIdx.x * 128;
    const int n0  = blockIdx.y * 128;
    const int tid = threadIdx.x;
    const int tx  = tid & 15;       // -> n
    const int ty  = tid >> 4;       // -> m

    const uint32_t as_sa = (uint32_t)__cvta_generic_to_shared(&As[0][0][0]);
    const uint32_t bs_sa = (uint32_t)__cvta_generic_to_shared(&Bs[0][0][0]);
    const int q0 = tid * 2;
    const int r0q = q0 >> 5, c0q = (q0 & 31) * 4;        // quad 0: row, col4
    const int r1q = (q0 + 1) >> 5, c1q = ((q0 + 1) & 31) * 4;

    auto load_stage = [&](int st, int kc) {
        uint32_t abase = as_sa + st * (16 * 132 * 4);
        uint32_t bbase = bs_sa + st * (16 * 132 * 4);
        cp16(abase + (r0q * 132 + c0q) * 4, AT + (size_t)(kc + r0q) * 8192 + m0 + c0q);
        cp16(abase + (r1q * 132 + c1q) * 4, AT + (size_t)(kc + r1q) * 8192 + m0 + c1q);
        cp16(bbase + (r0q * 132 + c0q) * 4, BT + (size_t)(kc + r0q) * 1024 + n0 + c0q);
        cp16(bbase + (r1q * 132 + c1q) * 4, BT + (size_t)(kc + r1q) * 1024 + n0 + c1q);
        asm volatile("cp.async.commit_group;" ::: "memory");
    };

    ull acc2[8][4];
#pragma unroll
    for (int i = 0; i < 8; i++)
#pragma unroll
        for (int j = 0; j < 4; j++) acc2[i][j] = 0ull;

    load_stage(0, 0);
#pragma unroll 1
    for (int it = 0; it < 16; ++it) {
        const int cur = it & 1;
        if (it < 15) load_stage(cur ^ 1, (it + 1) * 16);
        if (it < 15) asm volatile("cp.async.wait_group 1;" ::: "memory");
        else         asm volatile("cp.async.wait_group 0;" ::: "memory");
        __syncthreads();
#pragma unroll
        for (int k = 0; k < 16; k++) {
            float4 a0 = *reinterpret_cast<const float4*>(&As[cur][k][ty * 8]);
            float4 a1 = *reinterpret_cast<const float4*>(&As[cur][k][ty * 8 + 4]);
            ulonglong2 bb0 = *reinterpret_cast<const ulonglong2*>(&Bs[cur][k][tx * 8]);
            ulonglong2 bb1 = *reinterpret_cast<const ulonglong2*>(&Bs[cur][k][tx * 8 + 4]);
            ull b2[4] = { bb0.x, bb0.y, bb1.x, bb1.y };
            float av[8] = { a0.x, a0.y, a0.z, a0.w, a1.x, a1.y, a1.z, a1.w };
#pragma unroll
            for (int i = 0; i < 8; i++) {
                ull ap = pack2(av[i], av[i]);
#pragma unroll
                for (int j = 0; j < 4; j++) ffma2(acc2[i][j], ap, b2[j]);
            }
        }
        __syncthreads();
    }

    // epilogue: add bias, contiguous float4 stores
    float bv[8];
#pragma unroll
    for (int j = 0; j < 8; j++) bv[j] = bias[n0 + tx * 8 + j];
#pragma unroll
    for (int i = 0; i < 8; i++) {
        int m = m0 + ty * 8 + i;
        float2 e0 = unpack2(acc2[i][0]);
        float2 e1 = unpack2(acc2[i][1]);
        float2 e2 = unpack2(acc2[i][2]);
        float2 e3 = unpack2(acc2[i][3]);
        float4 o0, o1;
        o0.x = e0.x + bv[0]; o0.y = e0.y + bv[1];
        o0.z = e1.x + bv[2]; o0.w = e1.y + bv[3];
        o1.x = e2.x + bv[4]; o1.y = e2.y + bv[5];
        o1.z = e3.x + bv[6]; o1.w = e3.y + bv[7];
        float* dst = Xout + (size_t)m * G4_ + n0 + tx * 8;
        *reinterpret_cast<float4*>(dst)     = o0;
        *reinterpret_cast<float4*>(dst + 4) = o1;
    }
}

// ---------------------------------------------------------------------------
// K3: persistent BiLSTM recurrence.  Grid = 128 CTAs (64 per dir), 512 thr.
//     == R7 (proven 805 total) with ONE change: warp-internal lane remap.
//     Lane layout is now rq(4) x bq-octet(8) per warp (bq octet chosen by
//     the half-warp bit), so all 4 rq-duplicates of each h address sit in
//     the SAME warp and the LSU coalesces them into one L2 request.
//     Halves h L2 read traffic (128KB -> 64KB per CTA per step).
//     Barrier: R7's contended-atomic arrive + tid0 poll (measured best).
// ---------------------------------------------------------------------------
__global__ __launch_bounds__(512, 1) void k_steps(const int* __restrict__ lens,
                                                  const float* __restrict__ Whh_f,
                                                  const float* __restrict__ Whh_b) {
    __shared__ float w_s[256][16];        // [k][row]  16 KB (transposed Whh slice)
    __shared__ float part_s[8][16][64];   // k-slice partial gates  32 KB

    const int tid = threadIdx.x;
    const int dir = blockIdx.x >> 6;
    const int cb  = blockIdx.x & 63;
    const int j0  = cb * 4;
    const float* __restrict__ Whh = dir ? Whh_b : Whh_f;
    const float* __restrict__ X   = g_X + (size_t)dir * S_ * B_ * G4_;

    {
        int row = tid >> 5;                 // 0..15 (= gate*4 + ch)
        int gg  = row >> 2, ch = row & 3;
        int grw = gg * H_ + j0 + ch;
        const float* src = Whh + (size_t)grw * H_ + (tid & 31) * 8;
#pragma unroll
        for (int u = 0; u < 8; u += 4) {
            float4 v = *reinterpret_cast<const float4*>(src + u);
            int k0 = (tid & 31) * 8 + u;
            w_s[k0 + 0][row] = v.x;
            w_s[k0 + 1][row] = v.y;
            w_s[k0 + 2][row] = v.z;
            w_s[k0 + 3][row] = v.w;
        }
    }

    // GEMM-side ids: 512 = ks(8) x [warp-half -> bq octet] x rq(4) x bq_low(8)
    // Lane layout: lane = rq*8 + bq_low  => h addresses duplicated ONLY
    // within the warp (coalesced), never across warps.
    const int ks = tid >> 6;               // k-slice 0..7 (32 k each)
    const int rq = (tid >> 3) & 3;         // row quad 0..3
    const int bq = (((tid >> 5) & 1) << 3) | (tid & 7);   // batch quad 0..15
    const int r0 = rq * 4;
    const int b0 = bq * 4;
    const int kbase = ks * 32;

    const bool pw  = (tid < 256);
    const int  pch = tid >> 6;         // 0..3 channel within CTA (valid when pw)
    const int  pb  = tid & 63;         // batch
    const int  Lp  = pw ? __ldg(lens + pb) : 0;
    float creg = 0.0f;

    float* __restrict__ houtB = g_h + (size_t)dir * S_ * B_ * H_;
    int* barp = g_bar + dir * S_;

    float xg0 = 0.f, xg1 = 0.f, xg2 = 0.f, xg3 = 0.f;
    if (pw) {
        int m;
        if (dir == 0) m = pb;
        else { int rr = (0 < Lp) ? (Lp - 1) : 0; m = rr * B_ + pb; }
        const float* Xm = X + (size_t)m * G4_ + j0 + pch;
        xg0 = Xm[0 * H_]; xg1 = Xm[1 * H_]; xg2 = Xm[2 * H_]; xg3 = Xm[3 * H_];
    }
    __syncthreads();   // w_s ready

    for (int t = 0; t < S_; ++t) {
        if (t > 0) {
            ull a00 = 0, a01 = 0, a10 = 0, a11 = 0, a20 = 0, a21 = 0, a30 = 0, a31 = 0;
            const float* hsrc = &g_hT[dir][(t - 1) & 1][0][0] + (size_t)kbase * 64 + b0;
#pragma unroll 8
            for (int kk = 0; kk < 32; ++kk) {
                ull hx, hy;
                ldcg128(hx, hy, hsrc + kk * 64);
                float4 wv = *reinterpret_cast<const float4*>(&w_s[kbase + kk][r0]);
                ull w0 = pack2(wv.x, wv.x), w1 = pack2(wv.y, wv.y);
                ull w2 = pack2(wv.z, wv.z), w3 = pack2(wv.w, wv.w);
                ffma2(a00, w0, hx); ffma2(a01, w0, hy);
                ffma2(a10, w1, hx); ffma2(a11, w1, hy);
                ffma2(a20, w2, hx); ffma2(a21, w2, hy);
                ffma2(a30, w3, hx); ffma2(a31, w3, hy);
            }
            float2 l0 = unpack2(a00), h0 = unpack2(a01);
            float2 l1 = unpack2(a10), h1 = unpack2(a11);
            float2 l2 = unpack2(a20), h2v = unpack2(a21);
            float2 l3 = unpack2(a30), h3 = unpack2(a31);
            *reinterpret_cast<float4*>(&part_s[ks][r0 + 0][b0]) = make_float4(l0.x, l0.y, h0.x, h0.y);
            *reinterpret_cast<float4*>(&part_s[ks][r0 + 1][b0]) = make_float4(l1.x, l1.y, h1.x, h1.y);
            *reinterpret_cast<float4*>(&part_s[ks][r0 + 2][b0]) = make_float4(l2.x, l2.y, h2v.x, h2v.y);
            *reinterpret_cast<float4*>(&part_s[ks][r0 + 3][b0]) = make_float4(l3.x, l3.y, h3.x, h3.y);
            __syncthreads();
        }

        if (pw) {
            float gv0 = xg0, gv1 = xg1, gv2 = xg2, gv3 = xg3;
            if (t > 0) {
#pragma unroll
                for (int s = 0; s < 8; ++s) {
                    gv0 += part_s[s][0 * 4 + pch][pb];
                    gv1 += part_s[s][1 * 4 + pch][pb];
                    gv2 += part_s[s][2 * 4 + pch][pb];
                    gv3 += part_s[s][3 * 4 + pch][pb];
                }
            }
            float cn = fsig(gv1) * creg + fsig(gv0) * ftanh(gv2);
            float hn = fsig(gv3) * ftanh(cn);
            creg = cn;
            houtB[(size_t)t * B_ * H_ + pb * H_ + j0 + pch] = hn;
            stcg32(&g_hT[dir][t & 1][j0 + pch][pb], hn);
        }

        if (t < S_ - 1) {
            __syncthreads();                 // h(t) stores done CTA-wide
            // arrive FIRST (release orders the h stores)
            if (tid == 0)
                asm volatile("red.release.gpu.global.add.s32 [%0], 1;" :: "l"(barp + t) : "memory");

            // X(t+1) prefetch — overlaps barrier detection
            if (pw) {
                int tn = t + 1;
                int m;
                if (dir == 0) m = tn * B_ + pb;
                else { int rr = (tn < Lp) ? (Lp - 1 - tn) : tn; m = rr * B_ + pb; }
                const float* Xm = X + (size_t)m * G4_ + j0 + pch;
                xg0 = Xm[0 * H_]; xg1 = Xm[1 * H_]; xg2 = Xm[2 * H_]; xg3 = Xm[3 * H_];
            }

            // now wait
            if (tid == 0) {
                int guard = 1 << 20;
                int v;
                do {
                    asm volatile("ld.acquire.gpu.global.s32 %0, [%1];" : "=r"(v) : "l"(barp + t) : "memory");
                } while (v < NCTA_DIR && --guard);
            }
            __syncthreads();
        }
    }
}

// ---------------------------------------------------------------------------
// K4: u/w projections.  Block = (b, s-group of 8), 512 threads.
// ---------------------------------------------------------------------------
__global__ __launch_bounds__(512) void k_uw(const int* __restrict__ lens,
                                            const float* __restrict__ Ua,
                                            const float* __restrict__ Wa) {
    __shared__ float enc_s[8][516];

    const int b  = blockIdx.x;
    const int sg = blockIdx.y;
    const int tid = threadIdx.x;
    const int L = lens[b];

    {
        int lr = tid >> 6;             // local s row 0..7
        int lc = (tid & 63) * 8;       // col 0..504 step 8
        int s_row = sg * 8 + lr;
        bool valid = (s_row < L);
        int ridx = valid ? (L - 1 - s_row) : s_row;
        const float* src = (lc < 256)
            ? g_h + (size_t)s_row * B_ * H_ + b * H_ + lc
            : g_h + (size_t)S_ * B_ * H_ + (size_t)ridx * B_ * H_ + b * H_ + (lc - 256);
        float4 v0 = make_float4(0.f, 0.f, 0.f, 0.f);
        float4 v1 = v0;
        if (valid) {
            v0 = *reinterpret_cast<const float4*>(src);
            v1 = *reinterpret_cast<const float4*>(src + 4);
        }
        *reinterpret_cast<float4*>(&enc_s[lr][lc])     = v0;
        *reinterpret_cast<float4*>(&enc_s[lr][lc + 4]) = v1;
    }
    __syncthreads();

    const int row = tid >> 3;
    const int sl  = tid & 7;
    if (row < 2 * HID_) {
        const float* __restrict__ Wrow =
            (row < HID_) ? (Ua + (size_t)row * 2 * H_) : (Wa + (size_t)(row - HID_) * 2 * H_);
        float acc = 0.f;
#pragma unroll 8
        for (int k = 0; k < 2 * H_; k += 4) {
            float4 wv = *reinterpret_cast<const float4*>(Wrow + k);
            float4 ev = *reinterpret_cast<const float4*>(&enc_s[sl][k]);
            acc += wv.x * ev.x + wv.y * ev.y + wv.z * ev.z + wv.w * ev.w;
        }
        int s = sg * 8 + sl;
        if (row < HID_)
            g_U[((size_t)b * S_ + s) * HID_ + row] = acc;
        else
            g_Wt[(size_t)b * HID_ * S_ + (size_t)(row - HID_) * S_ + s] = acc;
    }
}

// ---------------------------------------------------------------------------
// K5: scores + predictions (MUFU tanh).
// ---------------------------------------------------------------------------
__global__ void k_scores(const float* __restrict__ va, float* __restrict__ out) {
    const int i = blockIdx.x;
    const int b = blockIdx.y;
    const int j = threadIdx.x;   // 128

    __shared__ float u_s[HID_];
    __shared__ float va_s[HID_];
    if (j < HID_) {
        u_s[j]  = g_U[((size_t)b * S_ + i) * HID_ + j];
        va_s[j] = va[j];
    }
    __syncthreads();

    const float* __restrict__ Wb = g_Wt + (size_t)b * HID_ * S_;
    float acc = 0.f;
#pragma unroll
    for (int k = 0; k < HID_; k++) {
        float wv = Wb[k * S_ + j];
        acc += ftanh(u_s[k] + wv) * va_s[k];
    }
    size_t idx = ((size_t)b * S_ + i) * S_ + j;
    out[idx] = acc;
    out[(size_t)B_ * S_ * S_ + idx] = (acc >= 0.0f) ? 1.0f : 0.0f;
}

// ---------------------------------------------------------------------------
extern "C" void kernel_launch(void* const* d_in, const int* in_sizes, int n_in,
                              void* d_out, int out_size) {
    const int*   concepts = (const int*)d_in[0];
    const int*   lens     = (const int*)d_in[1];
    const float* emb      = (const float*)d_in[2];
    const float* Wih_f    = (const float*)d_in[3];
    const float* Whh_f    = (const float*)d_in[4];
    const float* b_f      = (const float*)d_in[5];
    const float* Wih_b    = (const float*)d_in[6];
    const float* Whh_b    = (const float*)d_in[7];
    const float* b_b      = (const float*)d_in[8];
    const float* Ua       = (const float*)d_in[9];
    const float* Wa       = (const float*)d_in[10];
    const float* va       = (const float*)d_in[11];
    float* out = (float*)d_out;

    float* embT_p = nullptr;
    float* WihT_p = nullptr;
    float* emb_p  = nullptr;
    cudaGetSymbolAddress((void**)&embT_p, g_embT);
    cudaGetSymbolAddress((void**)&WihT_p, g_WihT);
    cudaGetSymbolAddress((void**)&emb_p,  g_emb);

    k_gather<<<S_ * B_, 64>>>(concepts, emb);
    k_transpose<<<dim3(E_ / 32, (S_ * B_) / 32), dim3(32, 8)>>>(emb_p, embT_p, S_ * B_, E_);
    k_transpose<<<dim3(E_ / 32, G4_ / 32), dim3(32, 8)>>>(Wih_f, WihT_p, G4_, E_);
    k_transpose<<<dim3(E_ / 32, G4_ / 32), dim3(32, 8)>>>(Wih_b, WihT_p + E_ * G4_, G4_, E_);
    k_xgemm<<<dim3(64, 8, 2), 256>>>(b_f, b_b);
    k_zero_bar<<<1, 256>>>();
    k_steps<<<2 * NCTA_DIR, 512>>>(lens, Whh_f, Whh_b);
    k_uw<<<dim3(B_, S_ / 8), 512>>>(lens, Ua, Wa);
    k_scores<<<dim3(S_, B_), 128>>>(va, out);
}